// round 14
// baseline (speedup 1.0000x reference)
#include <cuda_runtime.h>
#include <cstdint>

#define T_SEQ 2048
#define EMB   2048
#define NH    32
#define HD    64
#define LOG2E 1.4426950408889634f

// -------- scratch (device globals) --------
__device__ float g_Q[T_SEQ * EMB];      // q proj (scaled, rounded, D-permuted)
__device__ float g_K[T_SEQ * HD];       // k proj (rounded, D-permuted)
__device__ float g_V[HD * T_SEQ];       // v proj TRANSPOSED Vt[d][t], key-permuted
__device__ float g_A[T_SEQ * EMB];      // attention out (rounded, K-permuted cols)
__device__ float g_x [T_SEQ * EMB];     // x  rounded+permuted
__device__ float g_wq[EMB * EMB];       // Wq rounded+permuted
__device__ float g_wo[EMB * EMB];       // Wo rounded+permuted
__device__ float g_wk[HD * EMB];        // Wk rounded+permuted
__device__ float g_wv[HD * EMB];        // Wv rounded+permuted
__device__ float g_kvp[8 * T_SEQ * 128];// KV split-K partials

// ============================================================
// helpers
// ============================================================
__device__ __forceinline__ uint32_t smem_u32(const void* p) {
    uint32_t a;
    asm("{ .reg .u64 t; cvta.to.shared.u64 t, %1; cvt.u32.u64 %0, t; }" : "=r"(a) : "l"(p));
    return a;
}
__device__ __forceinline__ uint32_t f2tf32(float x) {
    uint32_t r;
    asm("cvt.rna.tf32.f32 %0, %1;" : "=r"(r) : "f"(x));
    return r;
}
__device__ __forceinline__ float rnd(float x) { return __uint_as_float(f2tf32(x)); }
__device__ __forceinline__ float fex2(float x) {
    float r;
    asm("ex2.approx.f32 %0, %1;" : "=f"(r) : "f"(x));
    return r;
}
__device__ __forceinline__ void cp16(uint32_t dst, const void* src) {
    asm volatile("cp.async.cg.shared.global [%0], [%1], 16;" :: "r"(dst), "l"(src) : "memory");
}
__device__ __forceinline__ void mma_tf32(float& d0, float& d1, float& d2, float& d3,
                                         uint32_t a0, uint32_t a1, uint32_t a2, uint32_t a3,
                                         uint32_t b0, uint32_t b1) {
    asm volatile("mma.sync.aligned.m16n8k8.row.col.f32.tf32.tf32.f32 "
                 "{%0,%1,%2,%3}, {%4,%5,%6,%7}, {%8,%9}, {%0,%1,%2,%3};"
                 : "+f"(d0), "+f"(d1), "+f"(d2), "+f"(d3)
                 : "r"(a0), "r"(a1), "r"(a2), "r"(a3), "r"(b0), "r"(b1));
}

// ============================================================
// fused round+permute prep: per 8-group out[2j]=in[j], out[2j+1]=in[j+4]
// ============================================================
#define NG_BIG (T_SEQ * EMB / 8)
#define NG_W   (HD * EMB / 8)

__global__ void prep_pass(const float* __restrict__ x,  const float* __restrict__ wq,
                          const float* __restrict__ wo, const float* __restrict__ wk,
                          const float* __restrict__ wv,
                          float* __restrict__ xr,  float* __restrict__ wqr,
                          float* __restrict__ wor, float* __restrict__ wkr,
                          float* __restrict__ wvr) {
    const int total = 3 * NG_BIG + 2 * NG_W;
    for (int gi = blockIdx.x * blockDim.x + threadIdx.x; gi < total;
         gi += gridDim.x * blockDim.x) {
        const float* src; float* dst; int off;
        if (gi < NG_BIG)                { src = x;  dst = xr;  off = gi; }
        else if (gi < 2 * NG_BIG)       { src = wq; dst = wqr; off = gi - NG_BIG; }
        else if (gi < 3 * NG_BIG)       { src = wo; dst = wor; off = gi - 2 * NG_BIG; }
        else if (gi < 3 * NG_BIG + NG_W){ src = wk; dst = wkr; off = gi - 3 * NG_BIG; }
        else                            { src = wv; dst = wvr; off = gi - 3 * NG_BIG - NG_W; }
        float4 a = *(const float4*)(src + (size_t)off * 8);
        float4 b = *(const float4*)(src + (size_t)off * 8 + 4);
        float4 o0 = make_float4(rnd(a.x), rnd(b.x), rnd(a.y), rnd(b.y));
        float4 o1 = make_float4(rnd(a.z), rnd(b.z), rnd(a.w), rnd(b.w));
        *(float4*)(dst + (size_t)off * 8)     = o0;
        *(float4*)(dst + (size_t)off * 8 + 4) = o1;
    }
}

// ============================================================
// tf32 mma.sync GEMM, K-permuted operands, 64x64 warp tiles.
// (unchanged from R11-R13)
// ============================================================
#define BKF 32
#define LDA 40
#define OPER_F (128 * LDA)
#define GEMM_SMEM (2 * 2 * OPER_F * 4)        // 81920 bytes

__global__ __launch_bounds__(128, 2) void gemm_tf32mma(
    const float* __restrict__ A, const float* __restrict__ B0,
    const float* __restrict__ B1, const float* __restrict__ B2,
    float* __restrict__ C, float* __restrict__ C2,
    int K, int N, int mode) {
    extern __shared__ float sm[];
    const int tid  = threadIdx.x;
    const int wid  = tid >> 5;
    const int lane = tid & 31;
    const int wm   = wid & 1;
    const int wn   = wid >> 1;
    const int g    = lane >> 2;
    const int tig  = lane & 3;

    int role, m0, n0, kbeg, NT, do_round, do_perm;
    float oscale;
    float* Cout;
    if (mode == 3) {
        if (blockIdx.x < 256) {
            role = 0; do_perm = 1; do_round = 1; oscale = 0.125f * LOG2E;
            n0 = (blockIdx.x & 15) * 128; m0 = (blockIdx.x >> 4) * 128;
            kbeg = 0; NT = K / BKF; Cout = C;
        } else {
            role = 2; do_perm = 0; do_round = 0; oscale = 1.0f;
            const int b = blockIdx.x - 256;
            kbeg = (b & 7) * 256; m0 = (b >> 3) * 128; n0 = 0; NT = 256 / BKF;
            Cout = C2 + (size_t)(b & 7) * T_SEQ * 128;
        }
    } else {
        role = 0; do_perm = 0; do_round = 0; oscale = 1.0f;
        n0 = blockIdx.x * 128; m0 = blockIdx.y * 128;
        kbeg = 0; NT = K / BKF; Cout = C;
    }

    float acc[4][8][4];
#pragma unroll
    for (int i = 0; i < 4; i++)
#pragma unroll
        for (int j = 0; j < 8; j++)
#pragma unroll
            for (int r = 0; r < 4; r++) acc[i][j][r] = 0.f;

    auto stage = [&](int t, int b) {
        float* dstA = sm + b * 2 * OPER_F;
        float* dstB = dstA + OPER_F;
        const int kof = kbeg + t * BKF;
#pragma unroll
        for (int u = 0; u < 8; u++) {
            int idx = u * 128 + tid;
            int r = idx >> 3, c4 = idx & 7;
            cp16(smem_u32(dstA + r * LDA + c4 * 4),
                 A + (size_t)(m0 + r) * K + kof + c4 * 4);
            const float* gb;
            if (role == 2) gb = (r < 64 ? B1 + (size_t)r * K : B2 + (size_t)(r - 64) * K)
                                + kof + c4 * 4;
            else           gb = B0 + (size_t)(n0 + r) * K + kof + c4 * 4;
            cp16(smem_u32(dstB + r * LDA + c4 * 4), gb);
        }
        asm volatile("cp.async.commit_group;" ::: "memory");
    };

    stage(0, 0);

    for (int t = 0; t < NT; t++) {
        if (t + 1 < NT) {
            stage(t + 1, (t + 1) & 1);
            asm volatile("cp.async.wait_group 1;" ::: "memory");
        } else {
            asm volatile("cp.async.wait_group 0;" ::: "memory");
        }
        __syncthreads();

        const float* sA = sm + (t & 1) * 2 * OPER_F + (wm * 64) * LDA;
        const float* sB = sm + (t & 1) * 2 * OPER_F + OPER_F + (wn * 64) * LDA;

#pragma unroll
        for (int ks = 0; ks < 4; ks++) {
            const int ko = ks * 8 + 2 * tig;
            uint32_t bf[8][2];
#pragma unroll
            for (int nt = 0; nt < 8; nt++) {
                float2 b = *(const float2*)(sB + (nt * 8 + g) * LDA + ko);
                bf[nt][0] = __float_as_uint(b.x);
                bf[nt][1] = __float_as_uint(b.y);
            }
            uint32_t af[4][4];
#pragma unroll
            for (int mt = 0; mt < 4; mt++) {
                float2 alo = *(const float2*)(sA + (mt * 16 + g) * LDA + ko);
                float2 ahi = *(const float2*)(sA + (mt * 16 + 8 + g) * LDA + ko);
                af[mt][0] = __float_as_uint(alo.x);
                af[mt][1] = __float_as_uint(ahi.x);
                af[mt][2] = __float_as_uint(alo.y);
                af[mt][3] = __float_as_uint(ahi.y);
            }
#pragma unroll
            for (int mt = 0; mt < 4; mt++)
#pragma unroll
                for (int nt = 0; nt < 8; nt++)
                    mma_tf32(acc[mt][nt][0], acc[mt][nt][1], acc[mt][nt][2], acc[mt][nt][3],
                             af[mt][0], af[mt][1], af[mt][2], af[mt][3],
                             bf[nt][0], bf[nt][1]);
        }
        __syncthreads();
    }

    const int cpa = 2 * ((2 * tig) & 3) + ((2 * tig) >> 2);
    const int cpb = 2 * ((2 * tig + 1) & 3) + ((2 * tig + 1) >> 2);
#pragma unroll
    for (int mt = 0; mt < 4; mt++) {
        const int row0 = m0 + wm * 64 + mt * 16 + g;
#pragma unroll
        for (int nt = 0; nt < 8; nt++) {
            float v0 = acc[mt][nt][0] * oscale, v1 = acc[mt][nt][1] * oscale;
            float v2 = acc[mt][nt][2] * oscale, v3 = acc[mt][nt][3] * oscale;
            if (do_round) { v0 = rnd(v0); v1 = rnd(v1); v2 = rnd(v2); v3 = rnd(v3); }
            const int colL = wn * 64 + nt * 8;
            if (role == 2) {
                const int c = colL + 2 * tig;
                *(float2*)(Cout + (size_t)row0 * 128 + c)       = make_float2(v0, v1);
                *(float2*)(Cout + (size_t)(row0 + 8) * 128 + c) = make_float2(v2, v3);
            } else if (do_perm) {
                const int cb = n0 + colL;
                Cout[(size_t)row0 * N + cb + cpa]       = v0;
                Cout[(size_t)row0 * N + cb + cpb]       = v1;
                Cout[(size_t)(row0 + 8) * N + cb + cpa] = v2;
                Cout[(size_t)(row0 + 8) * N + cb + cpb] = v3;
            } else {
                const int col = n0 + colL + 2 * tig;
                *(float2*)(Cout + (size_t)row0 * N + col)       = make_float2(v0, v1);
                *(float2*)(Cout + (size_t)(row0 + 8) * N + col) = make_float2(v2, v3);
            }
        }
    }
}

// ============================================================
// KV reduce (unchanged)
// ============================================================
__global__ void kv_reduce(const float* __restrict__ part,
                          float* __restrict__ Kd, float* __restrict__ Vt) {
    const int n4 = T_SEQ * 128 / 4;
    int idx = blockIdx.x * blockDim.x + threadIdx.x;
    if (idx >= n4) return;
    float4 s = *(const float4*)(part + (size_t)idx * 4);
#pragma unroll
    for (int p = 1; p < 8; p++) {
        float4 v = *(const float4*)(part + (size_t)p * T_SEQ * 128 + (size_t)idx * 4);
        s.x += v.x; s.y += v.y; s.z += v.z; s.w += v.w;
    }
    s.x = rnd(s.x); s.y = rnd(s.y); s.z = rnd(s.z); s.w = rnd(s.w);
    const int t = (idx * 4) >> 7;
    const int c = (idx * 4) & 127;
    if (c < 64) {
        const int base = t * 64 + (c & ~7);
        const int o = (c & 4) ? 1 : 0;
        Kd[base + o + 0] = s.x;
        Kd[base + o + 2] = s.y;
        Kd[base + o + 4] = s.z;
        Kd[base + o + 6] = s.w;
    } else {
        const int d = c - 64;
        const int permt = (t & ~7) + 2 * (t & 3) + ((t >> 2) & 1);
        Vt[(size_t)(d + 0) * T_SEQ + permt] = s.x;
        Vt[(size_t)(d + 1) * T_SEQ + permt] = s.y;
        Vt[(size_t)(d + 2) * T_SEQ + permt] = s.z;
        Vt[(size_t)(d + 3) * T_SEQ + permt] = s.w;
    }
}

// ============================================================
// Flash attention — 32-key tiles processed in DESCENDING j
// order (diagonal first). ALiBi monotonicity => running max is
// set by the first tiles; rescale skipped via __any_sync.
// Causal masking only on tiles straddling the diagonal.
// 3 smem buffers, one barrier per tile (R12 pipeline).
// ============================================================
#define SPK 72
#define SPV 40
#define SPP 40
#define TKEY 32
#define KBUF (TKEY * SPK)          // 2304 floats
#define VBUF (64 * SPV)            // 2560 floats
#define QROWS 64
#define ATT_SMEM ((3 * KBUF + 3 * VBUF + QROWS * SPP) * 4)   // 68608 B

__global__ __launch_bounds__(128, 3) void attn_mma(const float* __restrict__ Q,
                                                   const float* __restrict__ Kg,
                                                   const float* __restrict__ Vt,
                                                   float* __restrict__ O) {
    extern __shared__ float sm[];
    float* Kbase = sm;                       // 3 x [32][SPK]
    float* Vbase = sm + 3 * KBUF;            // 3 x [64][SPV]
    float* P     = sm + 3 * KBUF + 3 * VBUF; // [64][SPP]

    const int h   = blockIdx.y;
    const int q0  = (gridDim.x - 1 - blockIdx.x) * QROWS;   // largest-first
    const int tid = threadIdx.x;
    const int wid = tid >> 5;
    const int lane = tid & 31;
    const int g   = lane >> 2;
    const int tig = lane & 3;
    const float slope2 = exp2f(-0.25f * (float)(h + 1)) * LOG2E;

    // ---- stage Q (scaled/rounded/D-permuted) into K-buffer region ----
#pragma unroll
    for (int u = 0; u < 8; u++) {
        int idx = u * 128 + tid;
        int r = idx >> 4, c4 = idx & 15;
        *(float4*)(Kbase + r * SPK + c4 * 4) =
            *(const float4*)(Q + (size_t)(q0 + r) * EMB + h * HD + c4 * 4);
    }
    __syncthreads();

    uint32_t qf[8][4];
    {
        const float* QW = Kbase + wid * 16 * SPK;
#pragma unroll
        for (int ks = 0; ks < 8; ks++) {
            const int ko = ks * 8 + 2 * tig;
            float2 lo = *(const float2*)(QW + g * SPK + ko);
            float2 hi = *(const float2*)(QW + (g + 8) * SPK + ko);
            qf[ks][0] = __float_as_uint(lo.x);
            qf[ks][1] = __float_as_uint(hi.x);
            qf[ks][2] = __float_as_uint(lo.y);
            qf[ks][3] = __float_as_uint(hi.y);
        }
    }
    __syncthreads();   // all warps read Q before prefetch overwrites

    auto prefetch = [&](int t) {
        const int b = t % 3;
        const int j0 = t * TKEY;
        float* Kb = Kbase + b * KBUF;
        float* Vb = Vbase + b * VBUF;
#pragma unroll
        for (int u = 0; u < 4; u++) {
            int idx = u * 128 + tid;
            int kr = idx >> 4, kc = idx & 15;
            cp16(smem_u32(Kb + kr * SPK + kc * 4), Kg + (size_t)(j0 + kr) * HD + kc * 4);
            int vr = idx >> 3, vc = idx & 7;
            cp16(smem_u32(Vb + vr * SPV + vc * 4), Vt + (size_t)vr * T_SEQ + j0 + vc * 4);
        }
        asm volatile("cp.async.commit_group;" ::: "memory");
    };

    float oacc[8][4];
#pragma unroll
    for (int nt = 0; nt < 8; nt++)
#pragma unroll
        for (int r = 0; r < 4; r++) oacc[nt][r] = 0.f;

    float m0r = -1e30f, m1r = -1e30f;
    float l0 = 0.f, l1 = 0.f;
    const int i0 = q0 + wid * 16 + g;
    const int i1 = i0 + 8;
    const int imin = q0 + wid * 16;           // smallest row this warp owns
    float* PWm  = P + (wid * 16 + g) * SPP;
    float* PWm8 = PWm + 8 * SPP;
    const int cpa = 2 * ((2 * tig) & 3) + ((2 * tig) >> 2);
    const int cpb = 2 * ((2 * tig + 1) & 3) + ((2 * tig + 1) >> 2);

    const int NTILE = (q0 + QROWS) / TKEY;
    prefetch(NTILE - 1);

    for (int t = NTILE - 1; t >= 0; t--) {
        const int j0 = t * TKEY;
        if (t > 0) {
            prefetch(t - 1);     // buffer (t-1)%3: disjoint from t%3 and (t+1)%3
            asm volatile("cp.async.wait_group 1;" ::: "memory");
        } else {
            asm volatile("cp.async.wait_group 0;" ::: "memory");
        }
        __syncthreads();         // tile t visible; closes compute(t+1)

        const float* Ksh = Kbase + (t % 3) * KBUF;
        const float* Vsh = Vbase + (t % 3) * VBUF;

        // ---- S = Q @ K^T (32 keys) ----
        float sacc[4][4];
#pragma unroll
        for (int nt = 0; nt < 4; nt++)
#pragma unroll
            for (int r = 0; r < 4; r++) sacc[nt][r] = 0.f;

#pragma unroll
        for (int ks = 0; ks < 8; ks++) {
            const int ko = ks * 8 + 2 * tig;
#pragma unroll
            for (int nt = 0; nt < 4; nt++) {
                float2 b = *(const float2*)(Ksh + (nt * 8 + g) * SPK + ko);
                mma_tf32(sacc[nt][0], sacc[nt][1], sacc[nt][2], sacc[nt][3],
                         qf[ks][0], qf[ks][1], qf[ks][2], qf[ks][3],
                         __float_as_uint(b.x), __float_as_uint(b.y));
            }
        }

        // ---- ALiBi (+ causal mask only near the diagonal), tile max ----
        const bool need_mask = (j0 + TKEY - 1) > imin;
        float mx0 = -1e30f, mx1 = -1e30f;
        if (need_mask) {
#pragma unroll
            for (int nt = 0; nt < 4; nt++) {
                const int jb = j0 + nt * 8 + 2 * tig;
                float v0 = (jb     <= i0) ? fmaf(slope2, (float)(jb     - i0), sacc[nt][0]) : -1e30f;
                float v1 = (jb + 1 <= i0) ? fmaf(slope2, (float)(jb + 1 - i0), sacc[nt][1]) : -1e30f;
                float v2 = (jb     <= i1) ? fmaf(slope2, (float)(jb     - i1), sacc[nt][2]) : -1e30f;
                float v3 = (jb + 1 <= i1) ? fmaf(slope2, (float)(jb + 1 - i1), sacc[nt][3]) : -1e30f;
                sacc[nt][0] = v0; sacc[nt][1] = v1; sacc[nt][2] = v2; sacc[nt][3] = v3;
                mx0 = fmaxf(mx0, fmaxf(v0, v1));
                mx1 = fmaxf(mx1, fmaxf(v2, v3));
            }
        } else {
#pragma unroll
            for (int nt = 0; nt < 4; nt++) {
                const int jb = j0 + nt * 8 + 2 * tig;
                float v0 = fmaf(slope2, (float)(jb     - i0), sacc[nt][0]);
                float v1 = fmaf(slope2, (float)(jb + 1 - i0), sacc[nt][1]);
                float v2 = fmaf(slope2, (float)(jb     - i1), sacc[nt][2]);
                float v3 = fmaf(slope2, (float)(jb + 1 - i1), sacc[nt][3]);
                sacc[nt][0] = v0; sacc[nt][1] = v1; sacc[nt][2] = v2; sacc[nt][3] = v3;
                mx0 = fmaxf(mx0, fmaxf(v0, v1));
                mx1 = fmaxf(mx1, fmaxf(v2, v3));
            }
        }
        mx0 = fmaxf(mx0, __shfl_xor_sync(0xffffffffu, mx0, 1));
        mx0 = fmaxf(mx0, __shfl_xor_sync(0xffffffffu, mx0, 2));
        mx1 = fmaxf(mx1, __shfl_xor_sync(0xffffffffu, mx1, 1));
        mx1 = fmaxf(mx1, __shfl_xor_sync(0xffffffffu, mx1, 2));

        // clamp so fully-masked warps (all -1e30) still produce e == 0
        const float mn0 = fmaxf(fmaxf(m0r, mx0), -1e20f);
        const float mn1 = fmaxf(fmaxf(m1r, mx1), -1e20f);

        // rescale only when the running max actually moved (rare: descending
        // j means the diagonal tiles, processed first, set the max)
        const bool changed = (mn0 > m0r) || (mn1 > m1r);
        if (__any_sync(0xffffffffu, changed)) {
            const float a0 = fex2(m0r - mn0);
            const float a1 = fex2(m1r - mn1);
            l0 *= a0; l1 *= a1;
#pragma unroll
            for (int nt = 0; nt < 8; nt++) {
                oacc[nt][0] *= a0; oacc[nt][1] *= a0;
                oacc[nt][2] *= a1; oacc[nt][3] *= a1;
            }
            m0r = mn0; m1r = mn1;
        }

        float ps0 = 0.f, ps1 = 0.f;
#pragma unroll
        for (int nt = 0; nt < 4; nt++) {
            float e0 = fex2(sacc[nt][0] - m0r);
            float e1 = fex2(sacc[nt][1] - m0r);
            float e2 = fex2(sacc[nt][2] - m1r);
            float e3 = fex2(sacc[nt][3] - m1r);
            ps0 += e0 + e1;
            ps1 += e2 + e3;
            const int cb = nt * 8;
            PWm [cb + cpa] = rnd(e0);
            PWm [cb + cpb] = rnd(e1);
            PWm8[cb + cpa] = rnd(e2);
            PWm8[cb + cpb] = rnd(e3);
        }
        ps0 += __shfl_xor_sync(0xffffffffu, ps0, 1);
        ps0 += __shfl_xor_sync(0xffffffffu, ps0, 2);
        ps1 += __shfl_xor_sync(0xffffffffu, ps1, 1);
        ps1 += __shfl_xor_sync(0xffffffffu, ps1, 2);
        l0 += ps0;
        l1 += ps1;
        __syncwarp();

        // ---- O += P @ V  (32-key contraction = 4 k-steps) ----
        const float* PW = P + wid * 16 * SPP;
#pragma unroll
        for (int ks = 0; ks < 4; ks++) {
            const int ko = ks * 8 + 2 * tig;
            float2 plo = *(const float2*)(PW + g * SPP + ko);
            float2 phi = *(const float2*)(PW + (g + 8) * SPP + ko);
            uint32_t pa0 = __float_as_uint(plo.x);
            uint32_t pa1 = __float_as_uint(phi.x);
            uint32_t pa2 = __float_as_uint(plo.y);
            uint32_t pa3 = __float_as_uint(phi.y);
#pragma unroll
            for (int nt = 0; nt < 8; nt++) {
                float2 b = *(const float2*)(Vsh + (nt * 8 + g) * SPV + ko);
                mma_tf32(oacc[nt][0], oacc[nt][1], oacc[nt][2], oacc[nt][3],
                         pa0, pa1, pa2, pa3,
                         __float_as_uint(b.x), __float_as_uint(b.y));
            }
        }
    }

    // ---- normalize + store, K-permuted columns for the O-proj ----
    const float inv0 = 1.0f / l0;
    const float inv1 = 1.0f / l1;
    const int row0 = q0 + wid * 16 + g;
#pragma unroll
    for (int nt = 0; nt < 8; nt++) {
        const int base = h * HD + nt * 8;
        O[(size_t)row0 * EMB + base + cpa]       = rnd(oacc[nt][0] * inv0);
        O[(size_t)row0 * EMB + base + cpb]       = rnd(oacc[nt][1] * inv0);
        O[(size_t)(row0 + 8) * EMB + base + cpa] = rnd(oacc[nt][2] * inv1);
        O[(size_t)(row0 + 8) * EMB + base + cpb] = rnd(oacc[nt][3] * inv1);
    }
}

// ============================================================
// launch
// ============================================================
extern "C" void kernel_launch(void* const* d_in, const int* in_sizes, int n_in,
                              void* d_out, int out_size) {
    (void)in_sizes; (void)n_in; (void)out_size;
    const float* x  = (const float*)d_in[0];
    const float* Wq = (const float*)d_in[1];
    const float* Wk = (const float*)d_in[2];
    const float* Wv = (const float*)d_in[3];
    const float* Wo = (const float*)d_in[4];
    float* out = (float*)d_out;

    void *pQ, *pK, *pV, *pA, *px, *pwq, *pwo, *pwk, *pwv, *pkvp;
    cudaGetSymbolAddress(&pQ, g_Q);
    cudaGetSymbolAddress(&pK, g_K);
    cudaGetSymbolAddress(&pV, g_V);
    cudaGetSymbolAddress(&pA, g_A);
    cudaGetSymbolAddress(&px, g_x);
    cudaGetSymbolAddress(&pwq, g_wq);
    cudaGetSymbolAddress(&pwo, g_wo);
    cudaGetSymbolAddress(&pwk, g_wk);
    cudaGetSymbolAddress(&pwv, g_wv);
    cudaGetSymbolAddress(&pkvp, g_kvp);
    float* Qd = (float*)pQ;   float* Kd = (float*)pK;
    float* Vd = (float*)pV;   float* Ad = (float*)pA;
    float* xr = (float*)px;   float* wqr = (float*)pwq;
    float* wor = (float*)pwo; float* wkr = (float*)pwk;
    float* wvr = (float*)pwv; float* kvp = (float*)pkvp;

    cudaFuncSetAttribute(gemm_tf32mma, cudaFuncAttributeMaxDynamicSharedMemorySize, GEMM_SMEM);
    cudaFuncSetAttribute(attn_mma, cudaFuncAttributeMaxDynamicSharedMemorySize, ATT_SMEM);

    prep_pass<<<2048, 256>>>(x, Wq, Wo, Wk, Wv, xr, wqr, wor, wkr, wvr);

    gemm_tf32mma<<<384, 128, GEMM_SMEM>>>(
        xr, wqr, wkr, wvr, Qd, kvp, EMB, EMB, 3);
    kv_reduce<<<(T_SEQ * 128 / 4 + 255) / 256, 256>>>(kvp, Kd, Vd);
    attn_mma<<<dim3(T_SEQ / QROWS, NH), 128, ATT_SMEM>>>(Qd, Kd, Vd, Ad);
    gemm_tf32mma<<<dim3(EMB / 128, T_SEQ / 128), 128, GEMM_SMEM>>>(
        Ad, wor, nullptr, nullptr, out, nullptr, EMB, EMB, 0);
}